// round 13
// baseline (speedup 1.0000x reference)
#include <cuda_runtime.h>
#include <cuda_bf16.h>
#include <cstdint>

// Output: [32, 4096, 1024] fp32. out[..., c] = coef if (c odd && c < 1022) else 0.
// Pattern is periodic with period one row = 4KB. Each block fills a 16KB SMEM
// buffer (4 rows) once, then streams it to its contiguous 64KB global span via
// 4x cp.async.bulk (TMA-engine bulk stores) — bypassing the L1TEX/LSU store
// path entirely. 8192 blocks x 256 threads (known-good granularity).
//
// SMEM fill uses the established invariant: buffer float4 index = tid + k*256,
// within-row index = tid, so only tid==255 writes row-tail float4s and the
// fill value is a per-thread constant.

static constexpr int       THREADS        = 256;
static constexpr int       SMEM_VEC4      = 1024;                 // 16KB = 4 rows
static constexpr int       BULKS_PER_BLK  = 4;                    // 4 x 16KB = 64KB
static constexpr long long BYTES_PER_BLK  = 65536;
static constexpr long long TOTAL_BYTES    = 32LL * 4096LL * 1024LL * 4; // 512MB
static constexpr int       BLOCKS         = (int)(TOTAL_BYTES / BYTES_PER_BLK); // 8192

__global__ __launch_bounds__(THREADS)
void posenc_fill_kernel(char* __restrict__ out,
                        const float* __restrict__ coef_ptr) {
    __shared__ alignas(128) float4 buf[SMEM_VEC4];

    const float coef = __ldg(coef_ptr);
    const float w3 = (threadIdx.x == THREADS - 1) ? 0.0f : coef;
    const float4 val = make_float4(0.0f, coef, 0.0f, w3);

#pragma unroll
    for (int k = 0; k < SMEM_VEC4 / THREADS; ++k) {
        buf[threadIdx.x + k * THREADS] = val;
    }
    __syncthreads();
    // Order the generic-proxy SMEM writes before async-proxy bulk reads
    asm volatile("fence.proxy.async.shared::cta;" ::: "memory");

    if (threadIdx.x == 0) {
        uint32_t src;
        asm("{ .reg .u64 t; cvta.to.shared.u64 t, %1; cvt.u32.u64 %0, t; }"
            : "=r"(src) : "l"(buf));
        char* dst = out + (long long)blockIdx.x * BYTES_PER_BLK;
#pragma unroll
        for (int k = 0; k < BULKS_PER_BLK; ++k) {
            asm volatile(
                "cp.async.bulk.global.shared::cta.bulk_group [%0], [%1], %2;"
                :: "l"(dst + k * 16384), "r"(src), "n"(16384)
                : "memory");
        }
        asm volatile("cp.async.bulk.commit_group;" ::: "memory");
        asm volatile("cp.async.bulk.wait_group 0;" ::: "memory");
    }
}

extern "C" void kernel_launch(void* const* d_in, const int* in_sizes, int n_in,
                              void* d_out, int out_size) {
    const float* coef = (const float*)d_in[n_in - 1];  // coef_param is last input
    posenc_fill_kernel<<<BLOCKS, THREADS>>>((char*)d_out, coef);
}

// round 14
// speedup vs baseline: 1.0353x; 1.0353x over previous
#include <cuda_runtime.h>
#include <cuda_bf16.h>
#include <cstdint>

// FINAL KERNEL — PosEnc_60885456388113.
//
// Output: [32, 4096, 1024] fp32. out[..., c] = coef if (c odd && c < 1022) else 0.
// Row = 1024 floats = 256 float4s; all float4s are (0,coef,0,coef) except the
// last float4 of each row which is (0,coef,0,0).
//
// Pure 512MB broadcast write. Empirically at the sm_100a write floor
// (~6.45 TB/s, ~79% DRAM): invariant across store width (128/256b), cache
// policy (default/.CS/.WT), store path (LSU vs TMA bulk), granularity
// (1024..32768 blocks) and occupancy (20..91%). Best wall: this config,
// 75.8us (reproduced twice).
//
// Layout: 32768 blocks x 256 threads, 4 float4 stores per thread at stride
// 256 float4s (immediate offsets 0/4/8/12KB). VEC_PER_BLOCK = 1024 is a
// multiple of 256, so every store by thread t lands at within-row float4
// index t: only tid==255 ever writes a row-tail float4, making the store
// value a per-thread constant — zero per-iteration logic, ~1.5 instr/16B.

static constexpr long long TOTAL_VEC4     = 32LL * 4096LL * 1024LL / 4;  // 33,554,432
static constexpr int       THREADS        = 256;
static constexpr int       VEC_PER_THREAD = 4;
static constexpr int       VEC_PER_BLOCK  = THREADS * VEC_PER_THREAD;    // 1024
static constexpr int       BLOCKS         = (int)(TOTAL_VEC4 / VEC_PER_BLOCK); // 32768

__global__ __launch_bounds__(THREADS)
void posenc_fill_kernel(float4* __restrict__ out,
                        const float* __restrict__ coef_ptr) {
    const float coef = __ldg(coef_ptr);
    const float w3 = (threadIdx.x == THREADS - 1) ? 0.0f : coef;
    const float4 val = make_float4(0.0f, coef, 0.0f, w3);

    float4* p = out + (long long)blockIdx.x * VEC_PER_BLOCK + threadIdx.x;
#pragma unroll
    for (int k = 0; k < VEC_PER_THREAD; ++k) {
        p[k * THREADS] = val;   // STG.E.128 [Rbase + k*4096]
    }
}

extern "C" void kernel_launch(void* const* d_in, const int* in_sizes, int n_in,
                              void* d_out, int out_size) {
    const float* coef = (const float*)d_in[n_in - 1];  // coef_param is last input
    posenc_fill_kernel<<<BLOCKS, THREADS>>>((float4*)d_out, coef);
}

// round 15
// speedup vs baseline: 1.0414x; 1.0059x over previous
#include <cuda_runtime.h>
#include <cuda_bf16.h>
#include <cstdint>

// PosEnc_60885456388113 — final micro-variant probe.
//
// Output: [32, 4096, 1024] fp32. out[..., c] = coef if (c odd && c < 1022) else 0.
// Row = 1024 floats = 256 float4s; all float4s are (0,coef,0,coef) except the
// last float4 of each row which is (0,coef,0,0).
//
// Pure 512MB broadcast write at the sm_100a write floor (~6.45 TB/s, ~79%
// DRAM; invariant across store width, cache policy, LSU-vs-TMA path,
// granularity, occupancy). Last untested axis: threads-per-block. This probe:
// 512 threads x 4 float4 stores, 16384 blocks (halves per-block setup and
// scheduling events vs the 32768x256 best-wall config; everything else equal).
//
// VEC_PER_BLOCK = 2048, a multiple of 256, so every store by thread t lands
// at within-row float4 index (t & 255): only lanes with tid&255==255 ever
// write a row-tail float4 -> store value is a per-thread constant.

static constexpr long long TOTAL_VEC4     = 32LL * 4096LL * 1024LL / 4;  // 33,554,432
static constexpr int       THREADS        = 512;
static constexpr int       VEC_PER_THREAD = 4;
static constexpr int       VEC_PER_BLOCK  = THREADS * VEC_PER_THREAD;    // 2048
static constexpr int       BLOCKS         = (int)(TOTAL_VEC4 / VEC_PER_BLOCK); // 16384

__global__ __launch_bounds__(THREADS)
void posenc_fill_kernel(float4* __restrict__ out,
                        const float* __restrict__ coef_ptr) {
    const float coef = __ldg(coef_ptr);
    const float w3 = ((threadIdx.x & 255) == 255) ? 0.0f : coef;
    const float4 val = make_float4(0.0f, coef, 0.0f, w3);

    float4* p = out + (long long)blockIdx.x * VEC_PER_BLOCK + threadIdx.x;
#pragma unroll
    for (int k = 0; k < VEC_PER_THREAD; ++k) {
        p[k * THREADS] = val;   // STG.E.128 [Rbase + k*8192]
    }
}

extern "C" void kernel_launch(void* const* d_in, const int* in_sizes, int n_in,
                              void* d_out, int out_size) {
    const float* coef = (const float*)d_in[n_in - 1];  // coef_param is last input
    posenc_fill_kernel<<<BLOCKS, THREADS>>>((float4*)d_out, coef);
}

// round 17
// speedup vs baseline: 1.0418x; 1.0004x over previous
#include <cuda_runtime.h>
#include <cuda_bf16.h>
#include <cstdint>

// FINAL KERNEL — PosEnc_60885456388113 (search closed, round 15; resubmitted
// unchanged after an infra-side bench failure in round 16).
//
// Output: [32, 4096, 1024] fp32. out[..., c] = coef if (c odd && c < 1022) else 0.
// Row = 1024 floats = 256 float4s; all float4s are (0,coef,0,coef) except the
// last float4 of each row which is (0,coef,0,0).
//
// Pure 512MB broadcast write at the sm_100a pure-write DRAM floor
// (~6.45 TB/s sustained, ~79-81% DRAM active). The floor was shown invariant
// across: store width (STG.128/STG.256), cache policy (default/.CS/.WT),
// store path (LSU vs cp.async.bulk/TMA), block granularity (1024..32768),
// threads/block (256/512), and occupancy (20..91%). Real wins were
// instruction-count reduction (109->77.8us) and granularity (->75.8us).
//
// Layout: 32768 blocks x 256 threads, 4 float4 stores per thread at stride
// 256 float4s (immediate offsets 0/4/8/12KB). VEC_PER_BLOCK = 1024 is a
// multiple of 256, so every store by thread t lands at within-row float4
// index t: only tid==255 ever writes a row-tail float4, making the store
// value a per-thread constant — zero per-iteration logic, 26 regs,
// ~1.5 instructions per 16 bytes written.
//
// Best wall: 75.776us (reproduced across three clean runs of this shape).

static constexpr long long TOTAL_VEC4     = 32LL * 4096LL * 1024LL / 4;  // 33,554,432
static constexpr int       THREADS        = 256;
static constexpr int       VEC_PER_THREAD = 4;
static constexpr int       VEC_PER_BLOCK  = THREADS * VEC_PER_THREAD;    // 1024
static constexpr int       BLOCKS         = (int)(TOTAL_VEC4 / VEC_PER_BLOCK); // 32768

__global__ __launch_bounds__(THREADS)
void posenc_fill_kernel(float4* __restrict__ out,
                        const float* __restrict__ coef_ptr) {
    const float coef = __ldg(coef_ptr);
    const float w3 = (threadIdx.x == THREADS - 1) ? 0.0f : coef;
    const float4 val = make_float4(0.0f, coef, 0.0f, w3);

    float4* p = out + (long long)blockIdx.x * VEC_PER_BLOCK + threadIdx.x;
#pragma unroll
    for (int k = 0; k < VEC_PER_THREAD; ++k) {
        p[k * THREADS] = val;   // STG.E.128 [Rbase + k*4096]
    }
}

extern "C" void kernel_launch(void* const* d_in, const int* in_sizes, int n_in,
                              void* d_out, int out_size) {
    const float* coef = (const float*)d_in[n_in - 1];  // coef_param is last input
    posenc_fill_kernel<<<BLOCKS, THREADS>>>((float4*)d_out, coef);
}